// round 1
// baseline (speedup 1.0000x reference)
#include <cuda_runtime.h>

// Fixed problem geometry (B=32, C=5, 32^3 crop) -> 5,242,880 floats = 21 MB scratch.
#define ACC_ELEMS (32 * 5 * 32 * 32 * 32)

__device__ float        g_acc[ACC_ELEMS];
__device__ unsigned int g_maxabs;   // bits of a non-negative float (order-preserving as uint)

// ---------------------------------------------------------------------------
// Zero the accumulator and the max scalar.
__global__ void fm_init_kernel(int n) {
    int i = blockIdx.x * blockDim.x + threadIdx.x;
    if (i == 0) g_maxabs = 0u;
    for (; i < n; i += gridDim.x * blockDim.x) g_acc[i] = 0.0f;
}

// ---------------------------------------------------------------------------
// maxabs = max(|coords|) over all B*L*3 elements.
__global__ void fm_reduce_max_kernel(const float* __restrict__ coords, int n) {
    float m = 0.0f;
    for (int i = blockIdx.x * blockDim.x + threadIdx.x; i < n;
         i += gridDim.x * blockDim.x)
        m = fmaxf(m, fabsf(coords[i]));
#pragma unroll
    for (int o = 16; o; o >>= 1)
        m = fmaxf(m, __shfl_xor_sync(0xFFFFFFFFu, m, o));
    if ((threadIdx.x & 31) == 0)
        atomicMax(&g_maxabs, __float_as_uint(m));
}

// ---------------------------------------------------------------------------
// One block per (batch, atom) incl. 2 sentinel atoms. Each thread walks a
// strided subset of the 11^3 cube, keeps only entries inside the 32^3 crop
// window with exponent < 10, and atomically accumulates log1p(-exp(-e))
// directly in the output layout [B, C, X, Y, Z].
__global__ void fm_scatter_kernel(const float* __restrict__ coords,
                                  const int*   __restrict__ channel,
                                  const float* __restrict__ radius,
                                  int L, int L2) {
    const int a = blockIdx.x;
    const int b = a / L2;
    const int j = a - b * L2;

    // Derived scalars (all pure functions of g_maxabs; exact fp32 replication
    // of the reference: res = 0.5 so x/res == x*2 exactly).
    const float maxabs = __uint_as_float(g_maxabs);
    const float dumb   = maxabs + 10.0f;
    const float mmin   = truncf(-dumb * 2.0f);       // trunc(min/res), same all b,d
    const float transl = mmin - 5.0f;                // mincoords - CUBES_AROUND
    const int   box    = (int)(ceilf(dumb * 2.0f) - mmin) + 11;
    const int   lo     = (box + 1) / 2 - 16;         // crop start (global voxel idx)

    float px, py, pz, rad;
    int   ch;
    if (j < L) {
        const float* p = coords + ((size_t)b * L + j) * 3;
        px = p[0]; py = p[1]; pz = p[2];
        ch  = channel[(size_t)b * L + j];
        rad = radius [(size_t)b * L + j];
    } else {
        const float s = (j == L) ? -dumb : dumb;     // sentinel atoms
        px = py = pz = s;
        ch = 0;
        rad = 0.5f;                                  // ATOMIC_RADIUS
    }
    rad *= 1.41421356237309515f;                     // RADIUS_SCALE (f32)
    const float rt    = rad * 2.0f;                  // radius / res
    const float denom = 0.8649f * rt * rt;           // 0.93^2 * rt^2
    const float inv   = 1.0f / denom;

    const float tx = px * 2.0f - transl;             // coords_t (>= 0 for real atoms)
    const float ty = py * 2.0f - transl;
    const float tz = pz * 2.0f - transl;
    const int   dx = (int)truncf(tx);
    const int   dy = (int)truncf(ty);
    const int   dz = (int)truncf(tz);

    const int base_bc = (b * 5 + ch) * 32;

    for (int oi = threadIdx.x; oi < 11 * 11 * 11; oi += blockDim.x) {
        const int oz = oi % 11;
        const int t  = oi / 11;
        const int oy = t % 11;
        const int ox = t / 11;

        // global voxel index = disc + (o-5) + 1 = disc + o - 4
        const int ixg = dx + ox - 4;
        const int iyg = dy + oy - 4;
        const int izg = dz + oz - 4;

        const unsigned gx = (unsigned)(ixg - lo);
        const unsigned gy = (unsigned)(iyg - lo);
        const unsigned gz = (unsigned)(izg - lo);
        if ((gx | gy | gz) >= 32u) continue;         // outside the 32^3 crop

        // voxel center = global index + 0.5*res (0.25)
        const float ddx = tx - ((float)ixg + 0.25f);
        const float ddy = ty - ((float)iyg + 0.25f);
        const float ddz = tz - ((float)izg + 0.25f);
        const float d2  = ddx * ddx + ddy * ddy + ddz * ddz;
        const float e   = d2 * inv;
        if (e >= 10.0f) continue;                    // masked -> contributes 0

        const float val = log1pf(-expf(-e));
        const int idx = (((base_bc + (int)gx) * 32 + (int)gy) * 32) + (int)gz;
        atomicAdd(&g_acc[idx], val);
    }
}

// ---------------------------------------------------------------------------
// out = 1 - exp(acc)   (acc already in [B, C, X, Y, Z] layout)
__global__ void fm_finalize_kernel(float* __restrict__ out, int n) {
    for (int i = blockIdx.x * blockDim.x + threadIdx.x; i < n;
         i += gridDim.x * blockDim.x)
        out[i] = 1.0f - expf(g_acc[i]);
}

// ---------------------------------------------------------------------------
extern "C" void kernel_launch(void* const* d_in, const int* in_sizes, int n_in,
                              void* d_out, int out_size) {
    const float* coords = (const float*)d_in[0];   // [B, L, 3]
    const int*   chan   = (const int*)  d_in[1];   // [B, L]
    const float* rad    = (const float*)d_in[2];   // [B, L]

    const int BL = in_sizes[1];                    // B * L
    const int B  = out_size / (5 * 32 * 32 * 32);  // 32
    const int L  = BL / B;                         // 512
    const int L2 = L + 2;

    fm_init_kernel<<<264, 256>>>(out_size);
    fm_reduce_max_kernel<<<48, 256>>>(coords, in_sizes[0]);
    fm_scatter_kernel<<<B * L2, 256>>>(coords, chan, rad, L, L2);
    const int fb = (out_size + 255) / 256;
    fm_finalize_kernel<<<fb, 256>>>((float*)d_out, out_size);
}

// round 2
// speedup vs baseline: 1.1461x; 1.1461x over previous
#include <cuda_runtime.h>

__device__ float g_maxabs_f;   // max(|coords|), written by block 0 of init kernel

// ---------------------------------------------------------------------------
// Block 0: reduce max|coords| (no atomics, no pre-zero needed).
// Blocks 1..: zero the output accumulator (float4).
__global__ void fm_init_reduce_kernel(const float* __restrict__ coords, int ncoords,
                                      float4* __restrict__ out4, int n4) {
    if (blockIdx.x == 0) {
        float m = 0.0f;
        for (int i = threadIdx.x; i < ncoords; i += blockDim.x)
            m = fmaxf(m, fabsf(coords[i]));
        __shared__ float sm[32];
#pragma unroll
        for (int o = 16; o; o >>= 1)
            m = fmaxf(m, __shfl_xor_sync(0xFFFFFFFFu, m, o));
        if ((threadIdx.x & 31) == 0) sm[threadIdx.x >> 5] = m;
        __syncthreads();
        if (threadIdx.x < 32) {
            m = (threadIdx.x < (blockDim.x >> 5)) ? sm[threadIdx.x] : 0.0f;
#pragma unroll
            for (int o = 16; o; o >>= 1)
                m = fmaxf(m, __shfl_xor_sync(0xFFFFFFFFu, m, o));
            if (threadIdx.x == 0) g_maxabs_f = m;
        }
    } else {
        const float4 z = make_float4(0.f, 0.f, 0.f, 0.f);
        int i = (blockIdx.x - 1) * blockDim.x + threadIdx.x;
        const int stride = (gridDim.x - 1) * blockDim.x;
        for (; i < n4; i += stride) out4[i] = z;
    }
}

// ---------------------------------------------------------------------------
// One WARP per (batch, atom). Loop bounds pre-clipped per dimension to
//   [cube support] ∩ [cutoff-radius ball bounding box] ∩ [32^3 crop window],
// so the inner loop touches only candidate voxels. Entries skipped are exactly
// the reference's masked (e>=10) or out-of-crop entries -> contribute 0.
__global__ void fm_scatter_kernel(const float* __restrict__ coords,
                                  const int*   __restrict__ channel,
                                  const float* __restrict__ radius,
                                  int L, int L2, int nAtoms,
                                  float* __restrict__ acc) {
    const int wg   = (blockIdx.x * blockDim.x + threadIdx.x) >> 5;
    const int lane = threadIdx.x & 31;
    if (wg >= nAtoms) return;
    const int b = wg / L2;
    const int j = wg - b * L2;

    // Scalars derived from the global max (res = 0.5 -> x/res == x*2 exactly).
    const float maxabs = g_maxabs_f;
    const float dumb   = maxabs + 10.0f;
    const float mmin   = truncf(-dumb * 2.0f);       // trunc(min/res)
    const float transl = mmin - 5.0f;                // mincoords - CUBES_AROUND
    const int   box    = (int)(ceilf(dumb * 2.0f) - mmin) + 11;
    const int   lo     = (box + 1) / 2 - 16;         // crop start (global voxel idx)

    float px, py, pz, rad;
    int   ch;
    if (j < L) {
        const float* p = coords + ((size_t)b * L + j) * 3;
        px = p[0]; py = p[1]; pz = p[2];
        ch  = channel[(size_t)b * L + j];
        rad = radius [(size_t)b * L + j];
    } else {
        const float s = (j == L) ? -dumb : dumb;     // sentinel atoms
        px = py = pz = s;
        ch = 0;
        rad = 0.5f;
    }
    rad *= 1.41421356237309515f;                     // RADIUS_SCALE
    const float rt    = rad * 2.0f;                  // radius / res
    const float denom = 0.8649f * rt * rt;           // 0.93^2 * rt^2
    const float inv   = 1.0f / denom;
    const float rcut  = sqrtf(10.0f * denom) + 2e-3f;  // conservative cutoff radius

    const float tx = px * 2.0f - transl;
    const float ty = py * 2.0f - transl;
    const float tz = pz * 2.0f - transl;
    const int   dx = (int)truncf(tx);
    const int   dy = (int)truncf(ty);
    const int   dz = (int)truncf(tz);

    // Per-dim clipped global-voxel-index ranges.
    const int hi = lo + 31;
    int x0 = max(max(dx - 4, lo), (int)ceilf (tx - 0.25f - rcut));
    int x1 = min(min(dx + 6, hi), (int)floorf(tx - 0.25f + rcut));
    int y0 = max(max(dy - 4, lo), (int)ceilf (ty - 0.25f - rcut));
    int y1 = min(min(dy + 6, hi), (int)floorf(ty - 0.25f + rcut));
    int z0 = max(max(dz - 4, lo), (int)ceilf (tz - 0.25f - rcut));
    int z1 = min(min(dz + 6, hi), (int)floorf(tz - 0.25f + rcut));

    const int nx = x1 - x0 + 1, ny = y1 - y0 + 1, nz = z1 - z0 + 1;
    if (nx <= 0 || ny <= 0 || nz <= 0) return;
    const int total = nx * ny * nz;

    const int base_bc = (b * 5 + ch) * 32;

    for (int t = lane; t < total; t += 32) {
        const int izr = t % nz;
        const int q   = t / nz;
        const int iyr = q % ny;
        const int ixr = q / ny;
        const int gxi = x0 + ixr, gyi = y0 + iyr, gzi = z0 + izr;

        const float ddx = tx - ((float)gxi + 0.25f);
        const float ddy = ty - ((float)gyi + 0.25f);
        const float ddz = tz - ((float)gzi + 0.25f);
        const float d2  = ddx * ddx + ddy * ddy + ddz * ddz;
        const float e   = d2 * inv;
        if (e < 10.0f) {
            const float val = log1pf(-__expf(-e));
            const int idx = (((base_bc + (gxi - lo)) * 32 + (gyi - lo)) * 32) + (gzi - lo);
            atomicAdd(acc + idx, val);
        }
    }
}

// ---------------------------------------------------------------------------
// In-place: out = 1 - exp(out); zero stays zero (skips MUFU for empty voxels).
__global__ void fm_finalize_kernel(float4* __restrict__ out, int n4) {
    const int i = blockIdx.x * blockDim.x + threadIdx.x;
    if (i >= n4) return;
    float4 v = out[i];
    v.x = (v.x == 0.0f) ? 0.0f : 1.0f - __expf(v.x);
    v.y = (v.y == 0.0f) ? 0.0f : 1.0f - __expf(v.y);
    v.z = (v.z == 0.0f) ? 0.0f : 1.0f - __expf(v.z);
    v.w = (v.w == 0.0f) ? 0.0f : 1.0f - __expf(v.w);
    out[i] = v;
}

// ---------------------------------------------------------------------------
extern "C" void kernel_launch(void* const* d_in, const int* in_sizes, int n_in,
                              void* d_out, int out_size) {
    const float* coords = (const float*)d_in[0];   // [B, L, 3]
    const int*   chan   = (const int*)  d_in[1];   // [B, L]
    const float* rad    = (const float*)d_in[2];   // [B, L]

    const int BL = in_sizes[1];                    // B * L
    const int B  = out_size / (5 * 32 * 32 * 32);  // 32
    const int L  = BL / B;                         // 512
    const int L2 = L + 2;
    const int nAtoms = B * L2;
    const int n4 = out_size / 4;

    float* acc = (float*)d_out;

    fm_init_reduce_kernel<<<513, 256>>>(coords, in_sizes[0], (float4*)d_out, n4);
    const int sblocks = (nAtoms * 32 + 255) / 256;
    fm_scatter_kernel<<<sblocks, 256>>>(coords, chan, rad, L, L2, nAtoms, acc);
    fm_finalize_kernel<<<(n4 + 255) / 256, 256>>>((float4*)d_out, n4);
}

// round 3
// speedup vs baseline: 2.4893x; 2.1719x over previous
#include <cuda_runtime.h>

__device__ unsigned int g_maxabs_u;   // bits of max(|coords|) (non-negative float)

// ---------------------------------------------------------------------------
// K1: zero the output accumulator (float4); thread 0 resets the max scalar.
__global__ void fm_zero_kernel(float4* __restrict__ out4, int n4) {
    if (blockIdx.x == 0 && threadIdx.x == 0) g_maxabs_u = 0u;
    const float4 z = make_float4(0.f, 0.f, 0.f, 0.f);
    for (int i = blockIdx.x * blockDim.x + threadIdx.x; i < n4;
         i += gridDim.x * blockDim.x)
        out4[i] = z;
}

// ---------------------------------------------------------------------------
// K2: max|coords| over n4c float4s (one per thread), warp-reduce + atomicMax.
__global__ void fm_reduce_kernel(const float4* __restrict__ coords4, int n4c) {
    const int i = blockIdx.x * blockDim.x + threadIdx.x;
    float m = 0.0f;
    if (i < n4c) {
        float4 v = coords4[i];
        m = fmaxf(fmaxf(fabsf(v.x), fabsf(v.y)), fmaxf(fabsf(v.z), fabsf(v.w)));
    }
#pragma unroll
    for (int o = 16; o; o >>= 1)
        m = fmaxf(m, __shfl_xor_sync(0xFFFFFFFFu, m, o));
    if ((threadIdx.x & 31) == 0)
        atomicMax(&g_maxabs_u, __float_as_uint(m));
}

// ---------------------------------------------------------------------------
// K3: one WARP per (batch, atom). Lanes cover the clipped (x,y) footprint;
// each lane walks its short z-run with the xy-part of the exponent hoisted,
// skipping the whole run when the xy-part alone exceeds the cutoff.
__global__ void fm_scatter_kernel(const float* __restrict__ coords,
                                  const int*   __restrict__ channel,
                                  const float* __restrict__ radius,
                                  int L, int L2, int nAtoms,
                                  float* __restrict__ acc) {
    const int wg   = (blockIdx.x * blockDim.x + threadIdx.x) >> 5;
    const int lane = threadIdx.x & 31;
    if (wg >= nAtoms) return;
    const int b = wg / L2;
    const int j = wg - b * L2;

    // Scalars from the global max (res = 0.5 -> x/res == x*2 exactly).
    const float maxabs = __uint_as_float(g_maxabs_u);
    const float dumb   = maxabs + 10.0f;
    const float mmin   = truncf(-dumb * 2.0f);       // trunc(min/res)
    const float transl = mmin - 5.0f;                // mincoords - CUBES_AROUND
    const int   box    = (int)(ceilf(dumb * 2.0f) - mmin) + 11;
    const int   lo     = (box + 1) / 2 - 16;         // crop start (global voxel idx)

    float px, py, pz, rad;
    int   ch;
    if (j < L) {
        const float* p = coords + ((size_t)b * L + j) * 3;
        px = p[0]; py = p[1]; pz = p[2];
        ch  = channel[(size_t)b * L + j];
        rad = radius [(size_t)b * L + j];
    } else {
        const float s = (j == L) ? -dumb : dumb;     // sentinel atoms (never in crop)
        px = py = pz = s;
        ch = 0;
        rad = 0.5f;
    }
    rad *= 1.41421356237309515f;                     // RADIUS_SCALE
    const float rt    = rad * 2.0f;                  // radius / res
    const float denom = 0.8649f * rt * rt;           // 0.93^2 * rt^2
    const float inv   = 1.0f / denom;
    const float rcut  = sqrtf(10.0f * denom) + 2e-3f;

    const float tx = px * 2.0f - transl;
    const float ty = py * 2.0f - transl;
    const float tz = pz * 2.0f - transl;
    const int   dx = (int)truncf(tx);
    const int   dy = (int)truncf(ty);
    const int   dz = (int)truncf(tz);

    // Per-dim clipped global-voxel-index ranges: cube ∩ cutoff-box ∩ crop.
    const int hi = lo + 31;
    const int x0 = max(max(dx - 4, lo), (int)ceilf (tx - 0.25f - rcut));
    const int x1 = min(min(dx + 6, hi), (int)floorf(tx - 0.25f + rcut));
    const int y0 = max(max(dy - 4, lo), (int)ceilf (ty - 0.25f - rcut));
    const int y1 = min(min(dy + 6, hi), (int)floorf(ty - 0.25f + rcut));
    const int z0 = max(max(dz - 4, lo), (int)ceilf (tz - 0.25f - rcut));
    const int z1 = min(min(dz + 6, hi), (int)floorf(tz - 0.25f + rcut));

    const int nx = x1 - x0 + 1, ny = y1 - y0 + 1, nz = z1 - z0 + 1;
    if (nx <= 0 || ny <= 0 || nz <= 0) return;
    const int total_xy = nx * ny;

    const int base_bc = (b * 5 + ch) * 32;

    for (int t = lane; t < total_xy; t += 32) {
        const int iyr = t % ny;
        const int ixr = t / ny;
        const int gxi = x0 + ixr, gyi = y0 + iyr;

        const float ddx = tx - ((float)gxi + 0.25f);
        const float ddy = ty - ((float)gyi + 0.25f);
        const float exy = (ddx * ddx + ddy * ddy) * inv;
        if (exy >= 10.0f) continue;                  // whole z-run masked

        int idx = (((base_bc + (gxi - lo)) * 32 + (gyi - lo)) * 32) + (z0 - lo);
        float ddz = tz - ((float)z0 + 0.25f);
        for (int z = 0; z < nz; ++z, ++idx, ddz -= 1.0f) {
            const float e = fmaf(ddz * ddz, inv, exy);
            if (e < 10.0f) {
                const float val = __logf(1.0f - __expf(-e));
                atomicAdd(acc + idx, val);
            }
        }
    }
}

// ---------------------------------------------------------------------------
// K4: in-place out = 1 - exp(out); zero stays zero.
__global__ void fm_finalize_kernel(float4* __restrict__ out, int n4) {
    const int i = blockIdx.x * blockDim.x + threadIdx.x;
    if (i >= n4) return;
    float4 v = out[i];
    v.x = (v.x == 0.0f) ? 0.0f : 1.0f - __expf(v.x);
    v.y = (v.y == 0.0f) ? 0.0f : 1.0f - __expf(v.y);
    v.z = (v.z == 0.0f) ? 0.0f : 1.0f - __expf(v.z);
    v.w = (v.w == 0.0f) ? 0.0f : 1.0f - __expf(v.w);
    out[i] = v;
}

// ---------------------------------------------------------------------------
extern "C" void kernel_launch(void* const* d_in, const int* in_sizes, int n_in,
                              void* d_out, int out_size) {
    const float* coords = (const float*)d_in[0];   // [B, L, 3]
    const int*   chan   = (const int*)  d_in[1];   // [B, L]
    const float* rad    = (const float*)d_in[2];   // [B, L]

    const int BL = in_sizes[1];                    // B * L
    const int B  = out_size / (5 * 32 * 32 * 32);  // 32
    const int L  = BL / B;                         // 512
    const int L2 = L + 2;
    const int nAtoms = B * L2;
    const int n4  = out_size / 4;
    const int n4c = in_sizes[0] / 4;               // coords float4 count (49152/4)

    fm_zero_kernel<<<1024, 256>>>((float4*)d_out, n4);
    fm_reduce_kernel<<<(n4c + 255) / 256, 256>>>((const float4*)coords, n4c);
    const int sblocks = (nAtoms * 32 + 255) / 256;
    fm_scatter_kernel<<<sblocks, 256>>>(coords, chan, rad, L, L2, nAtoms, (float*)d_out);
    fm_finalize_kernel<<<(n4 + 255) / 256, 256>>>((float4*)d_out, n4);
}